// round 2
// baseline (speedup 1.0000x reference)
#include <cuda_runtime.h>

#define NTOK   2744
#define BATCH  4
#define CMID   256
#define CIN    1024
#define COUT   1024
#define NHEADS 4
#define DHEAD  64
#define WDIM   14

// ---------------- scratch (static device memory; no allocations) ----------------
__device__ float g_y1 [BATCH*CMID*NTOK];
__device__ float g_q  [BATCH*CMID*NTOK];
__device__ float g_k  [BATCH*CMID*NTOK];
__device__ float g_v  [BATCH*CMID*NTOK];
__device__ float g_vt [BATCH*NHEADS*NTOK*DHEAD];   // [b][h][m][d]
__device__ float g_rel[NHEADS*DHEAD*NTOK];
__device__ float g_ao [BATCH*CMID*NTOK];
__device__ float g_y3 [BATCH*COUT*NTOK];
__device__ float g_mean[1024];
__device__ float g_istd[1024];

// ---------------- rel position tensor: rel[h*64+d][n] ----------------
__global__ void build_rel_kernel(const float* __restrict__ rh,
                                 const float* __restrict__ rw,
                                 const float* __restrict__ rd) {
    int idx = blockIdx.x * 256 + threadIdx.x;          // < 4*64*2744
    int n  = idx % NTOK;
    int hd = idx / NTOK;
    int w  = n / (WDIM*WDIM);
    int hh = (n / WDIM) % WDIM;
    int dd = n % WDIM;
    g_rel[idx] = rh[(hd*WDIM + hh)*WDIM + dd]
               + rw[(hd*WDIM + w )*WDIM + dd]
               + rd[(hd*WDIM + w )*WDIM + hh];
}

// ---------------- generic NN GEMM: C[M,N] = A[M,K] @ B[K,N] (+bias per row) ----------------
__global__ __launch_bounds__(256) void gemm_nn(
    const float* __restrict__ A, const float* __restrict__ B, float* __restrict__ C,
    int M, int N, int K, long strideB, long strideC, const float* __restrict__ bias)
{
    __shared__ float As[8][132];
    __shared__ float Bs[8][132];
    B += (long)blockIdx.z * strideB;
    C += (long)blockIdx.z * strideC;
    const int bm = blockIdx.y * 128, bn = blockIdx.x * 128;
    const int tid = threadIdx.x;
    const int tx = tid & 15, ty = tid >> 4;

    const int a_row = tid >> 1;
    const int a_k4  = (tid & 1) * 4;
    const int b_k   = tid >> 5;
    const int b_n4  = (tid & 31) * 4;

    float acc[8][8] = {};

    for (int k0 = 0; k0 < K; k0 += 8) {
        float4 av = make_float4(0.f,0.f,0.f,0.f);
        int gm = bm + a_row;
        if (gm < M) av = *(const float4*)(A + (long)gm*K + k0 + a_k4);
        As[a_k4+0][a_row] = av.x; As[a_k4+1][a_row] = av.y;
        As[a_k4+2][a_row] = av.z; As[a_k4+3][a_row] = av.w;

        float4 bv = make_float4(0.f,0.f,0.f,0.f);
        int gn = bn + b_n4;
        if (gn < N) bv = *(const float4*)(B + (long)(k0 + b_k)*N + gn);
        *(float4*)&Bs[b_k][b_n4] = bv;
        __syncthreads();

        #pragma unroll
        for (int k = 0; k < 8; k++) {
            float4 a0 = *(float4*)&As[k][ty*8];
            float4 a1 = *(float4*)&As[k][ty*8+4];
            float4 b0 = *(float4*)&Bs[k][tx*8];
            float4 b1 = *(float4*)&Bs[k][tx*8+4];
            float a[8] = {a0.x,a0.y,a0.z,a0.w,a1.x,a1.y,a1.z,a1.w};
            float b[8] = {b0.x,b0.y,b0.z,b0.w,b1.x,b1.y,b1.z,b1.w};
            #pragma unroll
            for (int i = 0; i < 8; i++)
                #pragma unroll
                for (int j = 0; j < 8; j++)
                    acc[i][j] = fmaf(a[i], b[j], acc[i][j]);
        }
        __syncthreads();
    }
    #pragma unroll
    for (int i = 0; i < 8; i++) {
        int gm = bm + ty*8 + i;
        if (gm >= M) continue;
        float bi = bias ? bias[gm] : 0.f;
        #pragma unroll
        for (int j = 0; j < 8; j++) {
            int gn = bn + tx*8 + j;
            if (gn < N) C[(long)gm*N + gn] = acc[i][j] + bi;
        }
    }
}

// ---------------- transpose v[b][c][m] -> vt[b][h][m][d] ----------------
__global__ void transpose_v() {
    __shared__ float t[32][33];
    const int m0 = blockIdx.x * 32, c0 = blockIdx.y * 32, b = blockIdx.z;
    const int tx = threadIdx.x, ty = threadIdx.y;   // 32 x 8
    #pragma unroll
    for (int r = 0; r < 4; r++) {
        int c = c0 + ty + r*8;
        int m = m0 + tx;
        t[ty + r*8][tx] = (m < NTOK) ? g_v[((size_t)b*CMID + c)*NTOK + m] : 0.f;
    }
    __syncthreads();
    const int h = c0 >> 6, d0 = c0 & 63;
    #pragma unroll
    for (int r = 0; r < 4; r++) {
        int m = m0 + ty + r*8;
        if (m < NTOK)
            g_vt[((size_t)(b*NHEADS + h)*NTOK + m)*DHEAD + d0 + tx] = t[tx][ty + r*8];
    }
}

// ---------------- fused flash attention ----------------
// grid: (22 n-tiles, 16 bh), block 256. dyn smem: As+Bs+Ps+Vs
__global__ __launch_bounds__(256) void flash_attn() {
    extern __shared__ float smem[];
    float* As = smem;                  // 8*132
    float* Bs = As + 8*132;            // 8*132
    float* Ps = Bs + 8*132;            // 128*132  [m][n]
    float* Vs = Ps + 128*132;          // 8*68

    const int z = blockIdx.y, b = z >> 2, h = z & 3;
    const int n0 = blockIdx.x * 128;
    const float* Aq = g_q   + (size_t)(b*CMID + h*DHEAD)*NTOK;   // [64][N]
    const float* Ar = g_rel + (size_t)(h*DHEAD)*NTOK;
    const float* Bk = g_k   + (size_t)(b*CMID + h*DHEAD)*NTOK;
    const float* Vt = g_vt  + (size_t)z*NTOK*DHEAD;              // [m][64]
    float* Co = g_ao + (size_t)(b*CMID + h*DHEAD)*NTOK;

    const int tid = threadIdx.x;
    const int tx = tid & 15, ty = tid >> 4;
    const int lk  = tid >> 5;           // 0..7
    const int lc4 = (tid & 31) * 4;     // 0..124
    const int vrow = tid >> 5;          // 0..7
    const int vc2  = (tid & 31) * 2;    // 0..62

    float accO[8][4] = {};
    float Mr[8], Lr[8];
    #pragma unroll
    for (int i = 0; i < 8; i++) { Mr[i] = -1e30f; Lr[i] = 0.f; }

    for (int m0 = 0; m0 < NTOK; m0 += 128) {
        // ---- S tile: acc[i][j] = S[n0+ty*8+i][m0+tx*8+j] ----
        float acc[8][8] = {};
        #pragma unroll 1
        for (int k0 = 0; k0 < 2*DHEAD; k0 += 8) {
            int kk = k0 + lk;
            const float* ar = (kk < DHEAD) ? Aq + (size_t)kk*NTOK : Ar + (size_t)(kk-DHEAD)*NTOK;
            const float* br = (kk < DHEAD) ? Bk + (size_t)kk*NTOK : Aq + (size_t)(kk-DHEAD)*NTOK;
            float4 av = make_float4(0.f,0.f,0.f,0.f);
            float4 bv = make_float4(0.f,0.f,0.f,0.f);
            if (n0 + lc4 < NTOK) av = *(const float4*)(ar + n0 + lc4);
            if (m0 + lc4 < NTOK) bv = *(const float4*)(br + m0 + lc4);
            *(float4*)&As[lk*132 + lc4] = av;
            *(float4*)&Bs[lk*132 + lc4] = bv;
            __syncthreads();
            #pragma unroll
            for (int k = 0; k < 8; k++) {
                float4 a0 = *(float4*)&As[k*132 + ty*8];
                float4 a1 = *(float4*)&As[k*132 + ty*8 + 4];
                float4 b0 = *(float4*)&Bs[k*132 + tx*8];
                float4 b1 = *(float4*)&Bs[k*132 + tx*8 + 4];
                float a[8] = {a0.x,a0.y,a0.z,a0.w,a1.x,a1.y,a1.z,a1.w};
                float bb[8] = {b0.x,b0.y,b0.z,b0.w,b1.x,b1.y,b1.z,b1.w};
                #pragma unroll
                for (int i = 0; i < 8; i++)
                    #pragma unroll
                    for (int j = 0; j < 8; j++)
                        acc[i][j] = fmaf(a[i], bb[j], acc[i][j]);
            }
            __syncthreads();
        }

        // ---- mask invalid m columns ----
        #pragma unroll
        for (int j = 0; j < 8; j++) {
            if (m0 + tx*8 + j >= NTOK) {
                #pragma unroll
                for (int i = 0; i < 8; i++) acc[i][j] = -1e30f;
            }
        }

        // ---- online softmax (row reductions via shuffle over 16-lane groups) ----
        #pragma unroll
        for (int i = 0; i < 8; i++) {
            float mx = acc[i][0];
            #pragma unroll
            for (int j = 1; j < 8; j++) mx = fmaxf(mx, acc[i][j]);
            mx = fmaxf(mx, __shfl_xor_sync(0xffffffffu, mx, 1));
            mx = fmaxf(mx, __shfl_xor_sync(0xffffffffu, mx, 2));
            mx = fmaxf(mx, __shfl_xor_sync(0xffffffffu, mx, 4));
            mx = fmaxf(mx, __shfl_xor_sync(0xffffffffu, mx, 8));
            float newM = fmaxf(Mr[i], mx);
            float alpha = __expf(Mr[i] - newM);
            float s = 0.f;
            #pragma unroll
            for (int j = 0; j < 8; j++) {
                float p = __expf(acc[i][j] - newM);
                acc[i][j] = p;
                s += p;
            }
            s += __shfl_xor_sync(0xffffffffu, s, 1);
            s += __shfl_xor_sync(0xffffffffu, s, 2);
            s += __shfl_xor_sync(0xffffffffu, s, 4);
            s += __shfl_xor_sync(0xffffffffu, s, 8);
            Lr[i] = Lr[i]*alpha + s;
            Mr[i] = newM;
            #pragma unroll
            for (int jd = 0; jd < 4; jd++) accO[i][jd] *= alpha;
        }

        // ---- stage P to shared: Ps[m][n] ----
        #pragma unroll
        for (int j = 0; j < 8; j++)
            #pragma unroll
            for (int i = 0; i < 8; i++)
                Ps[(tx*8 + j)*132 + ty*8 + i] = acc[i][j];
        __syncthreads();

        // ---- O += P @ V  (V tile streamed in chunks of 8 m) ----
        #pragma unroll 1
        for (int c = 0; c < 16; c++) {
            {
                int gm = m0 + c*8 + vrow;
                float2 vv = make_float2(0.f, 0.f);
                if (gm < NTOK) vv = *(const float2*)(Vt + (size_t)gm*DHEAD + vc2);
                Vs[vrow*68 + vc2]     = vv.x;
                Vs[vrow*68 + vc2 + 1] = vv.y;
            }
            __syncthreads();
            #pragma unroll
            for (int mk = 0; mk < 8; mk++) {
                float4 p0 = *(float4*)&Ps[(c*8 + mk)*132 + ty*8];
                float4 p1 = *(float4*)&Ps[(c*8 + mk)*132 + ty*8 + 4];
                float4 vb = *(float4*)&Vs[mk*68 + tx*4];
                float pa[8] = {p0.x,p0.y,p0.z,p0.w,p1.x,p1.y,p1.z,p1.w};
                float vv[4] = {vb.x,vb.y,vb.z,vb.w};
                #pragma unroll
                for (int i = 0; i < 8; i++)
                    #pragma unroll
                    for (int jd = 0; jd < 4; jd++)
                        accO[i][jd] = fmaf(pa[i], vv[jd], accO[i][jd]);
            }
            __syncthreads();
        }
    }

    // ---- finalize: O / L, store to g_ao[d][n] ----
    #pragma unroll
    for (int i = 0; i < 8; i++) {
        int n = n0 + ty*8 + i;
        if (n >= NTOK) continue;
        float inv = 1.f / Lr[i];
        #pragma unroll
        for (int jd = 0; jd < 4; jd++)
            Co[(size_t)(tx*4 + jd)*NTOK + n] = accO[i][jd] * inv;
    }
}

// ---------------- BatchNorm (training-mode) stats per channel ----------------
__global__ __launch_bounds__(256) void bn_stats(const float* __restrict__ x, int C,
                                                float* __restrict__ mean, float* __restrict__ istd) {
    const int c = blockIdx.x;
    const int tid = threadIdx.x;
    float s = 0.f, sq = 0.f;
    for (int i = tid; i < BATCH*NTOK; i += 256) {
        int b = i / NTOK, n = i - b*NTOK;
        float v = x[((long)b*C + c)*NTOK + n];
        s += v; sq += v*v;
    }
    __shared__ float r1[256], r2[256];
    r1[tid] = s; r2[tid] = sq; __syncthreads();
    for (int st = 128; st > 0; st >>= 1) {
        if (tid < st) { r1[tid] += r1[tid+st]; r2[tid] += r2[tid+st]; }
        __syncthreads();
    }
    if (tid == 0) {
        const float inv_cnt = 1.f / (BATCH*NTOK);
        float m = r1[0] * inv_cnt;
        float var = r2[0] * inv_cnt - m*m;
        mean[c] = m;
        istd[c] = rsqrtf(var + 1e-5f);
    }
}

__global__ void bn_apply_relu(float* __restrict__ x, int C,
                              const float* __restrict__ mean, const float* __restrict__ istd,
                              const float* __restrict__ g, const float* __restrict__ bp) {
    long idx = (long)blockIdx.x * 256 + threadIdx.x;
    if (idx >= (long)BATCH*C*NTOK) return;
    int c = (int)((idx / NTOK) % C);
    float v = (x[idx] - mean[c]) * istd[c] * g[c] + bp[c];
    x[idx] = fmaxf(v, 0.f);
}

__global__ void bn_res_relu(const float* __restrict__ y, const float* __restrict__ xres,
                            float* __restrict__ out,
                            const float* __restrict__ mean, const float* __restrict__ istd,
                            const float* __restrict__ g, const float* __restrict__ bp) {
    long idx = (long)blockIdx.x * 256 + threadIdx.x;
    if (idx >= (long)BATCH*COUT*NTOK) return;
    int c = (int)((idx / NTOK) % COUT);
    float v = (y[idx] - mean[c]) * istd[c] * g[c] + bp[c] + xres[idx];
    out[idx] = fmaxf(v, 0.f);
}

// ---------------- launch ----------------
extern "C" void kernel_launch(void* const* d_in, const int* in_sizes, int n_in,
                              void* d_out, int out_size) {
    const float* x    = (const float*)d_in[0];
    const float* W1   = (const float*)d_in[1];
    const float* g1   = (const float*)d_in[2];
    const float* b1   = (const float*)d_in[3];
    const float* Wq   = (const float*)d_in[4];
    const float* bq   = (const float*)d_in[5];
    const float* Wk   = (const float*)d_in[6];
    const float* bk   = (const float*)d_in[7];
    const float* Wv   = (const float*)d_in[8];
    const float* bv   = (const float*)d_in[9];
    const float* relh = (const float*)d_in[10];
    const float* relw = (const float*)d_in[11];
    const float* reld = (const float*)d_in[12];
    const float* g2   = (const float*)d_in[13];
    const float* b2   = (const float*)d_in[14];
    const float* W3   = (const float*)d_in[15];
    const float* g3   = (const float*)d_in[16];
    const float* b3   = (const float*)d_in[17];
    float* out = (float*)d_out;

    float *y1, *q, *k, *v, *ao, *y3, *mean, *istd;
    cudaGetSymbolAddress((void**)&y1,  g_y1);
    cudaGetSymbolAddress((void**)&q,   g_q);
    cudaGetSymbolAddress((void**)&k,   g_k);
    cudaGetSymbolAddress((void**)&v,   g_v);
    cudaGetSymbolAddress((void**)&ao,  g_ao);
    cudaGetSymbolAddress((void**)&y3,  g_y3);
    cudaGetSymbolAddress((void**)&mean,g_mean);
    cudaGetSymbolAddress((void**)&istd,g_istd);

    const dim3 blk(256);
    const int NT = (NTOK + 127) / 128;   // 22
    const int FLASH_SMEM = (8*132 + 8*132 + 128*132 + 8*68) * 4;  // 78208 B
    cudaFuncSetAttribute(flash_attn, cudaFuncAttributeMaxDynamicSharedMemorySize, FLASH_SMEM);

    // conv1: [256,1024] @ x_b -> y1
    gemm_nn<<<dim3(NT, 2, BATCH), blk>>>(W1, x, y1, CMID, NTOK, CIN,
                                         (long)CIN*NTOK, (long)CMID*NTOK, nullptr);
    bn_stats<<<CMID, 256>>>(y1, CMID, mean, istd);
    bn_apply_relu<<<(BATCH*CMID*NTOK)/256, 256>>>(y1, CMID, mean, istd, g1, b1);

    // q,k,v projections (with bias)
    gemm_nn<<<dim3(NT, 2, BATCH), blk>>>(Wq, y1, q, CMID, NTOK, CMID,
                                         (long)CMID*NTOK, (long)CMID*NTOK, bq);
    gemm_nn<<<dim3(NT, 2, BATCH), blk>>>(Wk, y1, k, CMID, NTOK, CMID,
                                         (long)CMID*NTOK, (long)CMID*NTOK, bk);
    gemm_nn<<<dim3(NT, 2, BATCH), blk>>>(Wv, y1, v, CMID, NTOK, CMID,
                                         (long)CMID*NTOK, (long)CMID*NTOK, bv);

    // V transpose + relative position tensor
    transpose_v<<<dim3((NTOK+31)/32, CMID/32, BATCH), dim3(32,8)>>>();
    build_rel_kernel<<<(NHEADS*DHEAD*NTOK)/256, 256>>>(relh, relw, reld);

    // fused attention
    flash_attn<<<dim3(NT, BATCH*NHEADS), blk, FLASH_SMEM>>>();

    // BN2 + ReLU
    bn_stats<<<CMID, 256>>>(ao, CMID, mean, istd);
    bn_apply_relu<<<(BATCH*CMID*NTOK)/256, 256>>>(ao, CMID, mean, istd, g2, b2);

    // conv3: [1024,256] @ ao_b -> y3
    gemm_nn<<<dim3(NT, 8, BATCH), blk>>>(W3, ao, y3, COUT, NTOK, CMID,
                                         (long)CMID*NTOK, (long)COUT*NTOK, nullptr);
    bn_stats<<<COUT, 256>>>(y3, COUT, mean, istd);
    bn_res_relu<<<(BATCH*COUT*NTOK)/256, 256>>>(y3, x, out, mean, istd, g3, b3);
}

// round 3
// speedup vs baseline: 1.1077x; 1.1077x over previous
#include <cuda_runtime.h>

#define NTOK   2744
#define BATCH  4
#define CMID   256
#define CIN    1024
#define COUT   1024
#define NHEADS 4
#define DHEAD  64
#define WDIM   14

typedef unsigned long long u64;

__device__ __forceinline__ u64 pk2(float v) {
    u64 r; asm("mov.b64 %0, {%1,%1};" : "=l"(r) : "f"(v)); return r;
}
__device__ __forceinline__ void fma2(u64& d, u64 a, u64 b) {
    asm("fma.rn.f32x2 %0, %1, %2, %0;" : "+l"(d) : "l"(a), "l"(b));
}
__device__ __forceinline__ float2 up2(u64 v) {
    float2 f; asm("mov.b64 {%0,%1}, %2;" : "=f"(f.x), "=f"(f.y) : "l"(v)); return f;
}

// ---------------- scratch (static device memory; no allocations) ----------------
__device__ float g_y1 [BATCH*CMID*NTOK];
__device__ float g_q  [BATCH*CMID*NTOK];
__device__ float g_k  [BATCH*CMID*NTOK];
__device__ float g_v  [BATCH*CMID*NTOK];
__device__ float g_rel[NHEADS*DHEAD*NTOK];
__device__ float g_S  [(size_t)BATCH*NHEADS*NTOK*NTOK];   // ~482 MB
__device__ float g_ao [BATCH*CMID*NTOK];
__device__ float g_y3 [BATCH*COUT*NTOK];
__device__ float g_mean[1024];
__device__ float g_istd[1024];

// ---------------- rel position tensor: rel[h*64+d][n] ----------------
__global__ void build_rel_kernel(const float* __restrict__ rh,
                                 const float* __restrict__ rw,
                                 const float* __restrict__ rd) {
    int idx = blockIdx.x * 256 + threadIdx.x;
    int n  = idx % NTOK;
    int hd = idx / NTOK;
    int w  = n / (WDIM*WDIM);
    int hh = (n / WDIM) % WDIM;
    int dd = n % WDIM;
    g_rel[idx] = rh[(hd*WDIM + hh)*WDIM + dd]
               + rw[(hd*WDIM + w )*WDIM + dd]
               + rd[(hd*WDIM + w )*WDIM + hh];
}

// ---------------- NN GEMM: C[M,N] = A[M,K] @ B[K,N] (+bias), f32x2 + double buffer ----------------
__global__ __launch_bounds__(256) void gemm_nn(
    const float* __restrict__ A, const float* __restrict__ B, float* __restrict__ C,
    int M, int N, int K, long strideB, long strideC, const float* __restrict__ bias)
{
    __shared__ float As[2][8][132];
    __shared__ float Bs[2][8][132];
    B += (long)blockIdx.z * strideB;
    C += (long)blockIdx.z * strideC;
    const int bm = blockIdx.y * 128, bn = blockIdx.x * 128;
    const int tid = threadIdx.x;
    const int tx = tid & 15, ty = tid >> 4;

    const int a_row = tid >> 1;
    const int a_k4  = (tid & 1) * 4;
    const int b_k   = tid >> 5;
    const int b_n4  = (tid & 31) * 4;

    const int  gmA   = bm + a_row;
    const bool okA   = gmA < M;
    const int  gnB   = bn + b_n4;
    const bool okB   = gnB < N;
    const float4 z4 = make_float4(0.f,0.f,0.f,0.f);

    u64 acc[8][4] = {};

    const int S = K >> 3;
    float4 pa = okA ? *(const float4*)(A + (long)gmA*K + a_k4) : z4;
    float4 pb = okB ? *(const float4*)(B + (long)b_k*N + gnB)  : z4;

    for (int s = 0; s < S; s++) {
        const int buf = s & 1;
        As[buf][a_k4+0][a_row] = pa.x; As[buf][a_k4+1][a_row] = pa.y;
        As[buf][a_k4+2][a_row] = pa.z; As[buf][a_k4+3][a_row] = pa.w;
        *(float4*)&Bs[buf][b_k][b_n4] = pb;
        __syncthreads();

        if (s + 1 < S) {
            int k0 = (s + 1) * 8;
            pa = okA ? *(const float4*)(A + (long)gmA*K + k0 + a_k4)  : z4;
            pb = okB ? *(const float4*)(B + (long)(k0 + b_k)*N + gnB) : z4;
        }

        #pragma unroll
        for (int k = 0; k < 8; k++) {
            float4 a0 = *(float4*)&As[buf][k][ty*8];
            float4 a1 = *(float4*)&As[buf][k][ty*8+4];
            ulonglong2 bl0 = *(ulonglong2*)&Bs[buf][k][tx*8];
            ulonglong2 bl1 = *(ulonglong2*)&Bs[buf][k][tx*8+4];
            u64 bp[4] = {bl0.x, bl0.y, bl1.x, bl1.y};
            float a[8] = {a0.x,a0.y,a0.z,a0.w,a1.x,a1.y,a1.z,a1.w};
            #pragma unroll
            for (int i = 0; i < 8; i++) {
                u64 ai = pk2(a[i]);
                #pragma unroll
                for (int jp = 0; jp < 4; jp++) fma2(acc[i][jp], ai, bp[jp]);
            }
        }
        __syncthreads();
    }

    #pragma unroll
    for (int i = 0; i < 8; i++) {
        int gm = bm + ty*8 + i;
        if (gm >= M) continue;
        float bi = bias ? bias[gm] : 0.f;
        #pragma unroll
        for (int jp = 0; jp < 4; jp++) {
            float2 f = up2(acc[i][jp]);
            int gn = bn + tx*8 + jp*2;
            if (gn     < N) C[(long)gm*N + gn]     = f.x + bi;
            if (gn + 1 < N) C[(long)gm*N + gn + 1] = f.y + bi;
        }
    }
}

// ---------------- S = [q;rel]^T [k;q]   (TN GEMM, K=128), f32x2 + double buffer ----------------
__global__ __launch_bounds__(256) void gemm_tn_s() {
    const int z = blockIdx.z, b = z >> 2, h = z & 3;
    const float* Aq = g_q   + (size_t)(b*CMID + h*DHEAD)*NTOK;
    const float* Ar = g_rel + (size_t)(h*DHEAD)*NTOK;
    const float* Bk = g_k   + (size_t)(b*CMID + h*DHEAD)*NTOK;
    float* C = g_S + (size_t)z*NTOK*NTOK;

    __shared__ float As[2][8][132];
    __shared__ float Bs[2][8][132];
    const int tid = threadIdx.x;
    const int bm = blockIdx.y * 128, bn = blockIdx.x * 128;
    const int tx = tid & 15, ty = tid >> 4;
    const int lk  = tid >> 5;
    const int lc4 = (tid & 31) * 4;

    const bool okM = (bm + lc4) < NTOK;
    const bool okN = (bn + lc4) < NTOK;
    const float4 z4 = make_float4(0.f,0.f,0.f,0.f);

    u64 acc[8][4] = {};

    const int S = (2*DHEAD) >> 3;   // 16
    float4 pa, pb;
    {
        const float* ar = (lk < DHEAD) ? Aq + (size_t)lk*NTOK : Ar;
        const float* br = (lk < DHEAD) ? Bk + (size_t)lk*NTOK : Aq;
        pa = okM ? *(const float4*)(ar + bm + lc4) : z4;
        pb = okN ? *(const float4*)(br + bn + lc4) : z4;
    }

    for (int s = 0; s < S; s++) {
        const int buf = s & 1;
        *(float4*)&As[buf][lk][lc4] = pa;
        *(float4*)&Bs[buf][lk][lc4] = pb;
        __syncthreads();

        if (s + 1 < S) {
            int kk = (s + 1)*8 + lk;
            const float* ar = (kk < DHEAD) ? Aq + (size_t)kk*NTOK : Ar + (size_t)(kk-DHEAD)*NTOK;
            const float* br = (kk < DHEAD) ? Bk + (size_t)kk*NTOK : Aq + (size_t)(kk-DHEAD)*NTOK;
            pa = okM ? *(const float4*)(ar + bm + lc4) : z4;
            pb = okN ? *(const float4*)(br + bn + lc4) : z4;
        }

        #pragma unroll
        for (int k = 0; k < 8; k++) {
            float4 a0 = *(float4*)&As[buf][k][ty*8];
            float4 a1 = *(float4*)&As[buf][k][ty*8+4];
            ulonglong2 bl0 = *(ulonglong2*)&Bs[buf][k][tx*8];
            ulonglong2 bl1 = *(ulonglong2*)&Bs[buf][k][tx*8+4];
            u64 bp[4] = {bl0.x, bl0.y, bl1.x, bl1.y};
            float a[8] = {a0.x,a0.y,a0.z,a0.w,a1.x,a1.y,a1.z,a1.w};
            #pragma unroll
            for (int i = 0; i < 8; i++) {
                u64 ai = pk2(a[i]);
                #pragma unroll
                for (int jp = 0; jp < 4; jp++) fma2(acc[i][jp], ai, bp[jp]);
            }
        }
        __syncthreads();
    }

    #pragma unroll
    for (int i = 0; i < 8; i++) {
        int gm = bm + ty*8 + i;
        if (gm >= NTOK) continue;
        #pragma unroll
        for (int jp = 0; jp < 4; jp++) {
            float2 f = up2(acc[i][jp]);
            int gn = bn + tx*8 + jp*2;
            if (gn     < NTOK) C[(size_t)gm*NTOK + gn]     = f.x;
            if (gn + 1 < NTOK) C[(size_t)gm*NTOK + gn + 1] = f.y;
        }
    }
}

// ---------------- row softmax over m (in-place on g_S) ----------------
__global__ __launch_bounds__(256) void softmax_rows() {
    const size_t row = (size_t)blockIdx.y * NTOK + blockIdx.x;
    float* p = g_S + row * NTOK;
    const int tid = threadIdx.x;
    __shared__ float red[256];

    float vals[11];
    float m = -1e30f;
    #pragma unroll
    for (int i = 0; i < 11; i++) {
        int idx = tid + i*256;
        float v = (idx < NTOK) ? p[idx] : -1e30f;
        vals[i] = v;
        m = fmaxf(m, v);
    }
    red[tid] = m; __syncthreads();
    for (int s = 128; s > 0; s >>= 1) {
        if (tid < s) red[tid] = fmaxf(red[tid], red[tid+s]);
        __syncthreads();
    }
    m = red[0]; __syncthreads();

    float sum = 0.f;
    #pragma unroll
    for (int i = 0; i < 11; i++) {
        int idx = tid + i*256;
        if (idx < NTOK) { float e = __expf(vals[i] - m); vals[i] = e; sum += e; }
    }
    red[tid] = sum; __syncthreads();
    for (int s = 128; s > 0; s >>= 1) {
        if (tid < s) red[tid] += red[tid+s];
        __syncthreads();
    }
    float inv = 1.f / red[0];
    #pragma unroll
    for (int i = 0; i < 11; i++) {
        int idx = tid + i*256;
        if (idx < NTOK) p[idx] = vals[i] * inv;
    }
}

// ---------------- O[d,n] = sum_m V[d,m] * attn[n,m]  (per (b,h)), f32x2 + double buffer ----------------
__global__ __launch_bounds__(256) void gemm_av() {
    const int z = blockIdx.z, b = z >> 2, h = z & 3;
    const float* V = g_v + (size_t)(b*CMID + h*DHEAD)*NTOK;   // [64, N] m-contig
    const float* A = g_S + (size_t)z*NTOK*NTOK;               // [n, m]  m-contig
    float* C = g_ao + (size_t)(b*CMID + h*DHEAD)*NTOK;

    __shared__ float Vs[2][8][68];
    __shared__ float Bs[2][8][132];
    const int tid = threadIdx.x;
    const int bn = blockIdx.x * 128;
    const int tx = tid & 15, ty = tid >> 4;    // d0 = ty*4, n0 = tx*8
    const int lr  = tid >> 1;                  // 0..127
    const int lk4 = (tid & 1) * 4;

    const bool isV = tid < 128;                // lr = 0..63 -> d row
    const int  nA  = bn + lr;
    const bool okA = nA < NTOK;
    const float4 z4 = make_float4(0.f,0.f,0.f,0.f);

    u64 acc[4][4] = {};

    const int S = NTOK >> 3;   // 343
    float4 pv = isV ? *(const float4*)(V + (size_t)lr*NTOK + lk4) : z4;
    float4 pb = okA ? *(const float4*)(A + (size_t)nA*NTOK + lk4) : z4;

    for (int s = 0; s < S; s++) {
        const int buf = s & 1;
        if (isV) {
            Vs[buf][lk4+0][lr] = pv.x; Vs[buf][lk4+1][lr] = pv.y;
            Vs[buf][lk4+2][lr] = pv.z; Vs[buf][lk4+3][lr] = pv.w;
        }
        Bs[buf][lk4+0][lr] = pb.x; Bs[buf][lk4+1][lr] = pb.y;
        Bs[buf][lk4+2][lr] = pb.z; Bs[buf][lk4+3][lr] = pb.w;
        __syncthreads();

        if (s + 1 < S) {
            int k0 = (s + 1) * 8;
            if (isV) pv = *(const float4*)(V + (size_t)lr*NTOK + k0 + lk4);
            if (okA) pb = *(const float4*)(A + (size_t)nA*NTOK + k0 + lk4);
        }

        #pragma unroll
        for (int k = 0; k < 8; k++) {
            float4 vv = *(float4*)&Vs[buf][k][ty*4];
            ulonglong2 bl0 = *(ulonglong2*)&Bs[buf][k][tx*8];
            ulonglong2 bl1 = *(ulonglong2*)&Bs[buf][k][tx*8+4];
            u64 bp[4] = {bl0.x, bl0.y, bl1.x, bl1.y};
            float a[4] = {vv.x, vv.y, vv.z, vv.w};
            #pragma unroll
            for (int i = 0; i < 4; i++) {
                u64 ai = pk2(a[i]);
                #pragma unroll
                for (int jp = 0; jp < 4; jp++) fma2(acc[i][jp], ai, bp[jp]);
            }
        }
        __syncthreads();
    }

    #pragma unroll
    for (int i = 0; i < 4; i++) {
        int d = ty*4 + i;
        #pragma unroll
        for (int jp = 0; jp < 4; jp++) {
            float2 f = up2(acc[i][jp]);
            int n = bn + tx*8 + jp*2;
            if (n     < NTOK) C[(size_t)d*NTOK + n]     = f.x;
            if (n + 1 < NTOK) C[(size_t)d*NTOK + n + 1] = f.y;
        }
    }
}

// ---------------- BatchNorm (training-mode) stats per channel ----------------
__global__ __launch_bounds__(256) void bn_stats(const float* __restrict__ x, int C,
                                                float* __restrict__ mean, float* __restrict__ istd) {
    const int c = blockIdx.x;
    const int tid = threadIdx.x;
    float s = 0.f, sq = 0.f;
    for (int i = tid; i < BATCH*NTOK; i += 256) {
        int b = i / NTOK, n = i - b*NTOK;
        float v = x[((long)b*C + c)*NTOK + n];
        s += v; sq += v*v;
    }
    __shared__ float r1[256], r2[256];
    r1[tid] = s; r2[tid] = sq; __syncthreads();
    for (int st = 128; st > 0; st >>= 1) {
        if (tid < st) { r1[tid] += r1[tid+st]; r2[tid] += r2[tid+st]; }
        __syncthreads();
    }
    if (tid == 0) {
        const float inv_cnt = 1.f / (BATCH*NTOK);
        float m = r1[0] * inv_cnt;
        float var = r2[0] * inv_cnt - m*m;
        mean[c] = m;
        istd[c] = rsqrtf(var + 1e-5f);
    }
}

__global__ void bn_apply_relu(float* __restrict__ x, int C,
                              const float* __restrict__ mean, const float* __restrict__ istd,
                              const float* __restrict__ g, const float* __restrict__ bp) {
    long idx = (long)blockIdx.x * 256 + threadIdx.x;
    if (idx >= (long)BATCH*C*NTOK) return;
    int c = (int)((idx / NTOK) % C);
    float v = (x[idx] - mean[c]) * istd[c] * g[c] + bp[c];
    x[idx] = fmaxf(v, 0.f);
}

__global__ void bn_res_relu(const float* __restrict__ y, const float* __restrict__ xres,
                            float* __restrict__ out,
                            const float* __restrict__ mean, const float* __restrict__ istd,
                            const float* __restrict__ g, const float* __restrict__ bp) {
    long idx = (long)blockIdx.x * 256 + threadIdx.x;
    if (idx >= (long)BATCH*COUT*NTOK) return;
    int c = (int)((idx / NTOK) % COUT);
    float v = (y[idx] - mean[c]) * istd[c] * g[c] + bp[c] + xres[idx];
    out[idx] = fmaxf(v, 0.f);
}

// ---------------- launch ----------------
extern "C" void kernel_launch(void* const* d_in, const int* in_sizes, int n_in,
                              void* d_out, int out_size) {
    const float* x    = (const float*)d_in[0];
    const float* W1   = (const float*)d_in[1];
    const float* g1   = (const float*)d_in[2];
    const float* b1   = (const float*)d_in[3];
    const float* Wq   = (const float*)d_in[4];
    const float* bq   = (const float*)d_in[5];
    const float* Wk   = (const float*)d_in[6];
    const float* bk   = (const float*)d_in[7];
    const float* Wv   = (const float*)d_in[8];
    const float* bv   = (const float*)d_in[9];
    const float* relh = (const float*)d_in[10];
    const float* relw = (const float*)d_in[11];
    const float* reld = (const float*)d_in[12];
    const float* g2   = (const float*)d_in[13];
    const float* b2   = (const float*)d_in[14];
    const float* W3   = (const float*)d_in[15];
    const float* g3   = (const float*)d_in[16];
    const float* b3   = (const float*)d_in[17];
    float* out = (float*)d_out;

    float *y1, *q, *k, *v, *ao, *y3, *mean, *istd;
    cudaGetSymbolAddress((void**)&y1,  g_y1);
    cudaGetSymbolAddress((void**)&q,   g_q);
    cudaGetSymbolAddress((void**)&k,   g_k);
    cudaGetSymbolAddress((void**)&v,   g_v);
    cudaGetSymbolAddress((void**)&ao,  g_ao);
    cudaGetSymbolAddress((void**)&y3,  g_y3);
    cudaGetSymbolAddress((void**)&mean,g_mean);
    cudaGetSymbolAddress((void**)&istd,g_istd);

    const dim3 blk(256);
    const int NT = (NTOK + 127) / 128;   // 22

    // conv1: [256,1024] @ x_b -> y1
    gemm_nn<<<dim3(NT, 2, BATCH), blk>>>(W1, x, y1, CMID, NTOK, CIN,
                                         (long)CIN*NTOK, (long)CMID*NTOK, nullptr);
    bn_stats<<<CMID, 256>>>(y1, CMID, mean, istd);
    bn_apply_relu<<<(BATCH*CMID*NTOK)/256, 256>>>(y1, CMID, mean, istd, g1, b1);

    // q,k,v projections (with bias)
    gemm_nn<<<dim3(NT, 2, BATCH), blk>>>(Wq, y1, q, CMID, NTOK, CMID,
                                         (long)CMID*NTOK, (long)CMID*NTOK, bq);
    gemm_nn<<<dim3(NT, 2, BATCH), blk>>>(Wk, y1, k, CMID, NTOK, CMID,
                                         (long)CMID*NTOK, (long)CMID*NTOK, bk);
    gemm_nn<<<dim3(NT, 2, BATCH), blk>>>(Wv, y1, v, CMID, NTOK, CMID,
                                         (long)CMID*NTOK, (long)CMID*NTOK, bv);

    // relative position tensor
    build_rel_kernel<<<(NHEADS*DHEAD*NTOK)/256, 256>>>(relh, relw, reld);

    // attention logits + softmax + AV
    gemm_tn_s<<<dim3(NT, NT, BATCH*NHEADS), blk>>>();
    softmax_rows<<<dim3(NTOK, BATCH*NHEADS), blk>>>();
    gemm_av<<<dim3(NT, 1, BATCH*NHEADS), blk>>>();

    // BN2 + ReLU
    bn_stats<<<CMID, 256>>>(ao, CMID, mean, istd);
    bn_apply_relu<<<(BATCH*CMID*NTOK)/256, 256>>>(ao, CMID, mean, istd, g2, b2);

    // conv3: [1024,256] @ ao_b -> y3
    gemm_nn<<<dim3(NT, 8, BATCH), blk>>>(W3, ao, y3, COUT, NTOK, CMID,
                                         (long)CMID*NTOK, (long)COUT*NTOK, nullptr);
    bn_stats<<<COUT, 256>>>(y3, COUT, mean, istd);
    bn_res_relu<<<(BATCH*COUT*NTOK)/256, 256>>>(y3, x, out, mean, istd, g3, b3);
}

// round 4
// speedup vs baseline: 1.1762x; 1.0618x over previous
#include <cuda_runtime.h>

#define NTOK   2744
#define BATCH  4
#define CMID   256
#define CIN    1024
#define COUT   1024
#define NHEADS 4
#define DHEAD  64
#define WDIM   14

// ---------------- scratch (static device memory; no allocations) ----------------
__device__ float g_y1 [BATCH*CMID*NTOK];
__device__ float g_q  [BATCH*CMID*NTOK];
__device__ float g_k  [BATCH*CMID*NTOK];
__device__ float g_v  [BATCH*CMID*NTOK];
__device__ float g_rel[NHEADS*DHEAD*NTOK];
__device__ float g_S  [(size_t)BATCH*NHEADS*NTOK*NTOK];   // ~482 MB
__device__ float g_ao [BATCH*CMID*NTOK];
__device__ float g_y3 [BATCH*COUT*NTOK];
__device__ float g_mean[1024];
__device__ float g_istd[1024];

// ---------------- rel position tensor: rel[h*64+d][n] ----------------
__global__ void build_rel_kernel(const float* __restrict__ rh,
                                 const float* __restrict__ rw,
                                 const float* __restrict__ rd) {
    int idx = blockIdx.x * 256 + threadIdx.x;
    int n  = idx % NTOK;
    int hd = idx / NTOK;
    int w  = n / (WDIM*WDIM);
    int hh = (n / WDIM) % WDIM;
    int dd = n % WDIM;
    g_rel[idx] = rh[(hd*WDIM + hh)*WDIM + dd]
               + rw[(hd*WDIM + w )*WDIM + dd]
               + rd[(hd*WDIM + w )*WDIM + hh];
}

// ---------------- 64x128-tile GEMM core: C[M,N] = A[M,K] @ B[K,N] (+bias) ----------------
// 256 threads, 4x8 acc/thread, double-buffered smem, ONE sync per 8-k slab.
__device__ __forceinline__ void gemm_core64(
    const float* __restrict__ A, const float* __restrict__ B,
    float* __restrict__ C, int M, int N, int K,
    const float* __restrict__ bias, int bm, int bn,
    float (&As)[2][8][68], float (&Bs)[2][8][132])
{
    const int tid = threadIdx.x;
    const int tx = tid & 15, ty = tid >> 4;      // out: rows ty*4.., cols tx*8..
    const int a_row = tid >> 2, a_k2 = (tid & 3) * 2;
    const int b_k   = tid >> 5, b_n4 = (tid & 31) * 4;

    const int  gmA = bm + a_row;
    const bool okA = gmA < M;
    const int  gnB = bn + b_n4;
    const bool okB = gnB < N;

    float acc[4][8] = {};
    const int S = K >> 3;

    float2 pa = okA ? *(const float2*)(A + (long)gmA*K + a_k2) : make_float2(0.f, 0.f);
    float4 pb = okB ? *(const float4*)(B + (long)b_k*N + gnB)  : make_float4(0.f,0.f,0.f,0.f);

    for (int s = 0; s < S; s++) {
        const int buf = s & 1;
        As[buf][a_k2  ][a_row] = pa.x;
        As[buf][a_k2+1][a_row] = pa.y;
        *(float4*)&Bs[buf][b_k][b_n4] = pb;
        __syncthreads();

        if (s + 1 < S) {
            const int k0 = (s + 1) * 8;
            pa = okA ? *(const float2*)(A + (long)gmA*K + k0 + a_k2)  : make_float2(0.f, 0.f);
            pb = okB ? *(const float4*)(B + (long)(k0 + b_k)*N + gnB) : make_float4(0.f,0.f,0.f,0.f);
        }

        #pragma unroll
        for (int k = 0; k < 8; k++) {
            float4 av = *(float4*)&As[buf][k][ty*4];
            float4 b0 = *(float4*)&Bs[buf][k][tx*8];
            float4 b1 = *(float4*)&Bs[buf][k][tx*8+4];
            float a[4] = {av.x, av.y, av.z, av.w};
            float bb[8] = {b0.x,b0.y,b0.z,b0.w,b1.x,b1.y,b1.z,b1.w};
            #pragma unroll
            for (int i = 0; i < 4; i++)
                #pragma unroll
                for (int j = 0; j < 8; j++)
                    acc[i][j] = fmaf(a[i], bb[j], acc[i][j]);
        }
        // no trailing sync: next iter writes the other buffer
    }

    #pragma unroll
    for (int i = 0; i < 4; i++) {
        int gm = bm + ty*4 + i;
        if (gm >= M) continue;
        float bi = bias ? bias[gm] : 0.f;
        #pragma unroll
        for (int j = 0; j < 8; j++) {
            int gn = bn + tx*8 + j;
            if (gn < N) C[(long)gm*N + gn] = acc[i][j] + bi;
        }
    }
}

__global__ __launch_bounds__(256) void gemm64(
    const float* __restrict__ A, const float* __restrict__ B, float* __restrict__ C,
    int M, int N, int K, long strideB, long strideC, const float* __restrict__ bias)
{
    __shared__ float As[2][8][68];
    __shared__ float Bs[2][8][132];
    gemm_core64(A, B + (long)blockIdx.z*strideB, C + (long)blockIdx.z*strideC,
                M, N, K, bias, blockIdx.y*64, blockIdx.x*128, As, Bs);
}

// merged q/k/v projection: grid.y = 12 (mat*4 + mtile)
__global__ __launch_bounds__(256) void qkv_gemm(
    const float* __restrict__ Wq, const float* __restrict__ bq,
    const float* __restrict__ Wk, const float* __restrict__ bk,
    const float* __restrict__ Wv, const float* __restrict__ bv)
{
    __shared__ float As[2][8][68];
    __shared__ float Bs[2][8][132];
    const int my = blockIdx.y;
    const int mat = my >> 2;
    const int bm  = (my & 3) * 64;
    const long zoff = (long)blockIdx.z * CMID * NTOK;
    const float* A    = (mat == 0) ? Wq : (mat == 1) ? Wk : Wv;
    const float* bias = (mat == 0) ? bq : (mat == 1) ? bk : bv;
    float* C          = ((mat == 0) ? g_q : (mat == 1) ? g_k : g_v) + zoff;
    gemm_core64(A, g_y1 + zoff, C, CMID, NTOK, CMID, bias, bm, blockIdx.x*128, As, Bs);
}

// ---------------- S = [q;rel]^T [k;q]  (TN GEMM, K=128), scalar + 1-sync double buffer ----------------
__global__ __launch_bounds__(256) void gemm_tn_s() {
    const int z = blockIdx.z, b = z >> 2, h = z & 3;
    const float* Aq = g_q   + (size_t)(b*CMID + h*DHEAD)*NTOK;
    const float* Ar = g_rel + (size_t)(h*DHEAD)*NTOK;
    const float* Bk = g_k   + (size_t)(b*CMID + h*DHEAD)*NTOK;
    float* C = g_S + (size_t)z*NTOK*NTOK;

    __shared__ float As[2][8][132];
    __shared__ float Bs[2][8][132];
    const int tid = threadIdx.x;
    const int bm = blockIdx.y * 128, bn = blockIdx.x * 128;
    const int tx = tid & 15, ty = tid >> 4;
    const int lk  = tid >> 5;
    const int lc4 = (tid & 31) * 4;

    const bool okM = (bm + lc4) < NTOK;
    const bool okN = (bn + lc4) < NTOK;
    const float4 z4 = make_float4(0.f,0.f,0.f,0.f);

    float acc[8][8] = {};

    const int S = (2*DHEAD) >> 3;   // 16
    float4 pa, pb;
    {
        const float* ar = (lk < DHEAD) ? Aq + (size_t)lk*NTOK : Ar;
        const float* br = (lk < DHEAD) ? Bk + (size_t)lk*NTOK : Aq;
        pa = okM ? *(const float4*)(ar + bm + lc4) : z4;
        pb = okN ? *(const float4*)(br + bn + lc4) : z4;
    }

    for (int s = 0; s < S; s++) {
        const int buf = s & 1;
        *(float4*)&As[buf][lk][lc4] = pa;
        *(float4*)&Bs[buf][lk][lc4] = pb;
        __syncthreads();

        if (s + 1 < S) {
            int kk = (s + 1)*8 + lk;
            const float* ar = (kk < DHEAD) ? Aq + (size_t)kk*NTOK : Ar + (size_t)(kk-DHEAD)*NTOK;
            const float* br = (kk < DHEAD) ? Bk + (size_t)kk*NTOK : Aq + (size_t)(kk-DHEAD)*NTOK;
            pa = okM ? *(const float4*)(ar + bm + lc4) : z4;
            pb = okN ? *(const float4*)(br + bn + lc4) : z4;
        }

        #pragma unroll
        for (int k = 0; k < 8; k++) {
            float4 a0 = *(float4*)&As[buf][k][ty*8];
            float4 a1 = *(float4*)&As[buf][k][ty*8+4];
            float4 b0 = *(float4*)&Bs[buf][k][tx*8];
            float4 b1 = *(float4*)&Bs[buf][k][tx*8+4];
            float a[8] = {a0.x,a0.y,a0.z,a0.w,a1.x,a1.y,a1.z,a1.w};
            float bb[8] = {b0.x,b0.y,b0.z,b0.w,b1.x,b1.y,b1.z,b1.w};
            #pragma unroll
            for (int i = 0; i < 8; i++)
                #pragma unroll
                for (int j = 0; j < 8; j++)
                    acc[i][j] = fmaf(a[i], bb[j], acc[i][j]);
        }
    }

    #pragma unroll
    for (int i = 0; i < 8; i++) {
        int gm = bm + ty*8 + i;
        if (gm >= NTOK) continue;
        #pragma unroll
        for (int j = 0; j < 8; j++) {
            int gn = bn + tx*8 + j;
            if (gn < NTOK) C[(size_t)gm*NTOK + gn] = acc[i][j];
        }
    }
}

// ---------------- row softmax over m (in-place), warp-shuffle reductions ----------------
__global__ __launch_bounds__(256) void softmax_rows() {
    const size_t row = (size_t)blockIdx.y * NTOK + blockIdx.x;
    float* p = g_S + row * NTOK;
    const int tid = threadIdx.x;
    const int lane = tid & 31, wid = tid >> 5;
    __shared__ float redM[8], redS[8];

    float vals[11];
    float m = -1e30f;
    #pragma unroll
    for (int i = 0; i < 11; i++) {
        int idx = tid + i*256;
        float v = (idx < NTOK) ? p[idx] : -1e30f;
        vals[i] = v;
        m = fmaxf(m, v);
    }
    #pragma unroll
    for (int d = 16; d > 0; d >>= 1) m = fmaxf(m, __shfl_xor_sync(0xffffffffu, m, d));
    if (lane == 0) redM[wid] = m;
    __syncthreads();
    m = redM[0];
    #pragma unroll
    for (int w = 1; w < 8; w++) m = fmaxf(m, redM[w]);

    float sum = 0.f;
    #pragma unroll
    for (int i = 0; i < 11; i++) {
        int idx = tid + i*256;
        if (idx < NTOK) { float e = __expf(vals[i] - m); vals[i] = e; sum += e; }
    }
    #pragma unroll
    for (int d = 16; d > 0; d >>= 1) sum += __shfl_xor_sync(0xffffffffu, sum, d);
    if (lane == 0) redS[wid] = sum;
    __syncthreads();
    sum = redS[0];
    #pragma unroll
    for (int w = 1; w < 8; w++) sum += redS[w];

    float inv = 1.f / sum;
    #pragma unroll
    for (int i = 0; i < 11; i++) {
        int idx = tid + i*256;
        if (idx < NTOK) p[idx] = vals[i] * inv;
    }
}

// ---------------- O[d,n] = sum_m V[d,m] * attn[n,m]  (per (b,h)), 1-sync double buffer ----------------
__global__ __launch_bounds__(256) void gemm_av() {
    const int z = blockIdx.z, b = z >> 2, h = z & 3;
    const float* V = g_v + (size_t)(b*CMID + h*DHEAD)*NTOK;   // [64, N] m-contig
    const float* A = g_S + (size_t)z*NTOK*NTOK;               // [n, m]  m-contig
    float* C = g_ao + (size_t)(b*CMID + h*DHEAD)*NTOK;

    __shared__ float Vs[2][8][68];
    __shared__ float Bs[2][8][132];
    const int tid = threadIdx.x;
    const int bn = blockIdx.x * 128;
    const int tx = tid & 15, ty = tid >> 4;    // d0 = ty*4, n0 = tx*8
    const int lr  = tid >> 1;                  // 0..127
    const int lk4 = (tid & 1) * 4;

    const bool isV = tid < 128;                // lr = 0..63 -> d row
    const int  nA  = bn + lr;
    const bool okA = nA < NTOK;
    const float4 z4 = make_float4(0.f,0.f,0.f,0.f);

    float acc[4][8] = {};

    const int S = NTOK >> 3;   // 343
    float4 pv = isV ? *(const float4*)(V + (size_t)lr*NTOK + lk4) : z4;
    float4 pb = okA ? *(const float4*)(A + (size_t)nA*NTOK + lk4) : z4;

    for (int s = 0; s < S; s++) {
        const int buf = s & 1;
        if (isV) {
            Vs[buf][lk4+0][lr] = pv.x; Vs[buf][lk4+1][lr] = pv.y;
            Vs[buf][lk4+2][lr] = pv.z; Vs[buf][lk4+3][lr] = pv.w;
        }
        Bs[buf][lk4+0][lr] = pb.x; Bs[buf][lk4+1][lr] = pb.y;
        Bs[buf][lk4+2][lr] = pb.z; Bs[buf][lk4+3][lr] = pb.w;
        __syncthreads();

        if (s + 1 < S) {
            int k0 = (s + 1) * 8;
            if (isV) pv = *(const float4*)(V + (size_t)lr*NTOK + k0 + lk4);
            if (okA) pb = *(const float4*)(A + (size_t)nA*NTOK + k0 + lk4);
        }

        #pragma unroll
        for (int k = 0; k < 8; k++) {
            float4 vv = *(float4*)&Vs[buf][k][ty*4];
            float4 b0 = *(float4*)&Bs[buf][k][tx*8];
            float4 b1 = *(float4*)&Bs[buf][k][tx*8+4];
            float a[4] = {vv.x, vv.y, vv.z, vv.w};
            float bb[8] = {b0.x,b0.y,b0.z,b0.w,b1.x,b1.y,b1.z,b1.w};
            #pragma unroll
            for (int i = 0; i < 4; i++)
                #pragma unroll
                for (int j = 0; j < 8; j++)
                    acc[i][j] = fmaf(a[i], bb[j], acc[i][j]);
        }
    }

    #pragma unroll
    for (int i = 0; i < 4; i++) {
        int d = ty*4 + i;
        #pragma unroll
        for (int j = 0; j < 8; j++) {
            int n = bn + tx*8 + j;
            if (n < NTOK) C[(size_t)d*NTOK + n] = acc[i][j];
        }
    }
}

// ---------------- BatchNorm (training-mode) stats per channel ----------------
__global__ __launch_bounds__(256) void bn_stats(const float* __restrict__ x, int C,
                                                float* __restrict__ mean, float* __restrict__ istd) {
    const int c = blockIdx.x;
    const int tid = threadIdx.x;
    const int lane = tid & 31, wid = tid >> 5;
    float s = 0.f, sq = 0.f;
    for (int i = tid; i < BATCH*NTOK; i += 256) {
        int b = i / NTOK, n = i - b*NTOK;
        float v = x[((long)b*C + c)*NTOK + n];
        s += v; sq += v*v;
    }
    #pragma unroll
    for (int d = 16; d > 0; d >>= 1) {
        s  += __shfl_xor_sync(0xffffffffu, s, d);
        sq += __shfl_xor_sync(0xffffffffu, sq, d);
    }
    __shared__ float r1[8], r2[8];
    if (lane == 0) { r1[wid] = s; r2[wid] = sq; }
    __syncthreads();
    if (tid == 0) {
        float S1 = 0.f, S2 = 0.f;
        #pragma unroll
        for (int w = 0; w < 8; w++) { S1 += r1[w]; S2 += r2[w]; }
        const float inv_cnt = 1.f / (BATCH*NTOK);
        float m = S1 * inv_cnt;
        float var = S2 * inv_cnt - m*m;
        mean[c] = m;
        istd[c] = rsqrtf(var + 1e-5f);
    }
}

__global__ void bn_apply_relu(float* __restrict__ x, int C,
                              const float* __restrict__ mean, const float* __restrict__ istd,
                              const float* __restrict__ g, const float* __restrict__ bp) {
    long idx = (long)blockIdx.x * 256 + threadIdx.x;
    if (idx >= (long)BATCH*C*NTOK) return;
    int c = (int)((idx / NTOK) % C);
    float v = (x[idx] - mean[c]) * istd[c] * g[c] + bp[c];
    x[idx] = fmaxf(v, 0.f);
}

__global__ void bn_res_relu(const float* __restrict__ y, const float* __restrict__ xres,
                            float* __restrict__ out,
                            const float* __restrict__ mean, const float* __restrict__ istd,
                            const float* __restrict__ g, const float* __restrict__ bp) {
    long idx = (long)blockIdx.x * 256 + threadIdx.x;
    if (idx >= (long)BATCH*COUT*NTOK) return;
    int c = (int)((idx / NTOK) % COUT);
    float v = (y[idx] - mean[c]) * istd[c] * g[c] + bp[c] + xres[idx];
    out[idx] = fmaxf(v, 0.f);
}

// ---------------- launch ----------------
extern "C" void kernel_launch(void* const* d_in, const int* in_sizes, int n_in,
                              void* d_out, int out_size) {
    const float* x    = (const float*)d_in[0];
    const float* W1   = (const float*)d_in[1];
    const float* g1   = (const float*)d_in[2];
    const float* b1   = (const float*)d_in[3];
    const float* Wq   = (const float*)d_in[4];
    const float* bq   = (const float*)d_in[5];
    const float* Wk   = (const float*)d_in[6];
    const float* bk   = (const float*)d_in[7];
    const float* Wv   = (const float*)d_in[8];
    const float* bv   = (const float*)d_in[9];
    const float* relh = (const float*)d_in[10];
    const float* relw = (const float*)d_in[11];
    const float* reld = (const float*)d_in[12];
    const float* g2   = (const float*)d_in[13];
    const float* b2   = (const float*)d_in[14];
    const float* W3   = (const float*)d_in[15];
    const float* g3   = (const float*)d_in[16];
    const float* b3   = (const float*)d_in[17];
    float* out = (float*)d_out;

    float *y1, *ao, *y3, *mean, *istd;
    cudaGetSymbolAddress((void**)&y1,  g_y1);
    cudaGetSymbolAddress((void**)&ao,  g_ao);
    cudaGetSymbolAddress((void**)&y3,  g_y3);
    cudaGetSymbolAddress((void**)&mean,g_mean);
    cudaGetSymbolAddress((void**)&istd,g_istd);

    const dim3 blk(256);
    const int NT = (NTOK + 127) / 128;   // 22

    // conv1: [256,1024] @ x_b -> y1   (64-row tiles: grid 22x4x4 = 352)
    gemm64<<<dim3(NT, 4, BATCH), blk>>>(W1, x, y1, CMID, NTOK, CIN,
                                        (long)CIN*NTOK, (long)CMID*NTOK, nullptr);
    bn_stats<<<CMID, 256>>>(y1, CMID, mean, istd);
    bn_apply_relu<<<(BATCH*CMID*NTOK)/256, 256>>>(y1, CMID, mean, istd, g1, b1);

    // q,k,v projections merged (grid 22x12x4 = 1056)
    qkv_gemm<<<dim3(NT, 12, BATCH), blk>>>(Wq, bq, Wk, bk, Wv, bv);

    // relative position tensor
    build_rel_kernel<<<(NHEADS*DHEAD*NTOK)/256, 256>>>(relh, relw, reld);

    // attention logits + softmax + AV
    gemm_tn_s<<<dim3(NT, NT, BATCH*NHEADS), blk>>>();
    softmax_rows<<<dim3(NTOK, BATCH*NHEADS), blk>>>();
    gemm_av<<<dim3(NT, 1, BATCH*NHEADS), blk>>>();

    // BN2 + ReLU
    bn_stats<<<CMID, 256>>>(ao, CMID, mean, istd);
    bn_apply_relu<<<(BATCH*CMID*NTOK)/256, 256>>>(ao, CMID, mean, istd, g2, b2);

    // conv3: [1024,256] @ ao_b -> y3  (grid 22x16x4 = 1408)
    gemm64<<<dim3(NT, 16, BATCH), blk>>>(W3, ao, y3, COUT, NTOK, CMID,
                                         (long)CMID*NTOK, (long)COUT*NTOK, nullptr);
    bn_stats<<<COUT, 256>>>(y3, COUT, mean, istd);
    bn_res_relu<<<(BATCH*COUT*NTOK)/256, 256>>>(y3, x, out, mean, istd, g3, b3);
}